// round 15
// baseline (speedup 1.0000x reference)
#include <cuda_runtime.h>
#include <cuda_bf16.h>
#include <math.h>
#include <cstdint>

#define BB 32
#define MM 1024
#define NN 1024

typedef unsigned int u32;
typedef unsigned short u16;

// ---------------- scratch (no allocations allowed) ----------------
__device__ float g_part[2][BB * MM];  // per n-half sqrt-sums
__device__ float g_dish[BB * MM];
__device__ float g_lpart[256];
__device__ int   g_which[BB];
__device__ float g_Rbest[BB][12];
__device__ int   g_done;              // zero-init; self-resetting each run

// ---------------- helpers ----------------
__device__ __forceinline__ u32 smem_u32(const void* p) {
    u32 a; asm("{ .reg .u64 t; cvta.to.shared.u64 t, %1; cvt.u32.u64 %0, t; }" : "=r"(a) : "l"(p));
    return a;
}
__device__ __forceinline__ float sqrt_approx(float x) {
    float r; asm("sqrt.approx.f32 %0, %1;" : "=f"(r) : "f"(x)); return r;
}
__device__ __forceinline__ void mma16816(float& d0, float& d1, float& d2, float& d3,
                                         u32 a0, u32 a1, u32 a2, u32 a3, u32 b0, u32 b1) {
    asm volatile(
        "mma.sync.aligned.m16n8k16.row.col.f32.bf16.bf16.f32 "
        "{%0,%1,%2,%3}, {%4,%5,%6,%7}, {%8,%9}, {%0,%1,%2,%3};"
        : "+f"(d0), "+f"(d1), "+f"(d2), "+f"(d3)
        : "r"(a0), "r"(a1), "r"(a2), "r"(a3), "r"(b0), "r"(b1));
}
__device__ __forceinline__ void ldsm_x4(u32& r0, u32& r1, u32& r2, u32& r3, u32 addr) {
    asm volatile("ldmatrix.sync.aligned.m8n8.x4.shared.b16 {%0,%1,%2,%3}, [%4];"
                 : "=r"(r0), "=r"(r1), "=r"(r2), "=r"(r3) : "r"(addr));
}
__device__ __forceinline__ void ldsm_x2(u32& r0, u32& r1, u32 addr) {
    asm volatile("ldmatrix.sync.aligned.m8n8.x2.shared.b16 {%0,%1}, [%2];"
                 : "=r"(r0), "=r"(r1) : "r"(addr));
}
__device__ __forceinline__ void split_bf16(float v, u16& h, u16& l) {
    __nv_bfloat16 hb = __float2bfloat16(v);
    float r = v - __bfloat162float(hb);
    __nv_bfloat16 lb = __float2bfloat16(r);
    h = __bfloat16_as_ushort(hb);
    l = __bfloat16_as_ushort(lb);
}

// quat (xyzw) + t -> 12 floats: R row-major then t
__device__ __forceinline__ void quat_to_Rt(float qx, float qy, float qz, float qw,
                                           float t0, float t1, float t2, float* o) {
    float nrm = sqrtf(qx * qx + qy * qy + qz * qz + qw * qw);
    float inv = __fdividef(1.0f, nrm + 1e-8f);
    qx *= inv; qy *= inv; qz *= inv; qw *= inv;
    o[0] = 1.0f - 2.0f * (qy * qy + qz * qz);
    o[1] = 2.0f * (qx * qy - qz * qw);
    o[2] = 2.0f * (qx * qz + qy * qw);
    o[3] = 2.0f * (qx * qy + qz * qw);
    o[4] = 1.0f - 2.0f * (qx * qx + qz * qz);
    o[5] = 2.0f * (qy * qz - qx * qw);
    o[6] = 2.0f * (qx * qz - qy * qw);
    o[7] = 2.0f * (qy * qz + qx * qw);
    o[8] = 1.0f - 2.0f * (qx * qx + qy * qy);
    o[9] = t0; o[10] = t1; o[11] = t2;
}

// pack 17 split values into a 64-col bf16 row, write swizzled into smem words
__device__ __forceinline__ void emit_row(u32* sm, int row, const float* v17, bool hhl) {
    u16 col[64];
    #pragma unroll
    for (int k = 0; k < 64; k++) col[k] = 0;
    #pragma unroll
    for (int k = 0; k < 17; k++) {
        u16 h, l; split_bf16(v17[k], h, l);
        if (hhl) { col[k] = h; col[17 + k] = h; col[34 + k] = l; }   // P: [h,h,l]
        else     { col[k] = h; col[17 + k] = l; col[34 + k] = h; }   // Q: [h,l,h]
    }
    u32 rx = (u32)((row & 7) << 4);
    #pragma unroll
    for (int j = 0; j < 32; j++) {
        u32 wv = (u32)col[2 * j] | ((u32)col[2 * j + 1] << 16);
        u32 off = ((u32)(row * 128 + j * 4)) ^ rx;
        sm[off >> 2] = wv;
    }
}

// ---------------- K1: fused prep + HMMA main ----------------
// grid (2 nhalf, 16 mtile, 32 b), 128 thr = 4 warps, warp owns one m16 tile.
// dyn smem: A 64x64 bf16 (8KB) + B 512x64 bf16 (64KB), row%8 16B-xor swizzle.
__global__ void __launch_bounds__(128) k_main(const float* __restrict__ pred_r,
                                              const float* __restrict__ pred_t,
                                              const float* __restrict__ pred_c,
                                              const float* __restrict__ points,
                                              const float* __restrict__ mp,
                                              const float* __restrict__ tg) {
    extern __shared__ __align__(16) u32 dsm[];
    u32* smA = dsm;            // 2048 u32
    u32* smB = dsm + 2048;     // 16384 u32
    const int nh = blockIdx.x;
    const int mt = blockIdx.y;
    const int b  = blockIdx.z;
    const int t  = threadIdx.x;
    const int w  = t >> 5;
    const int lane = t & 31;
    const u32 aA = smem_u32(smA);
    const u32 aB = smem_u32(smB);

    // ---- build Q rows (4 per thread) directly into smB ----
    #pragma unroll
    for (int j4 = 0; j4 < 4; j4++) {
        int r = t + j4 * 128;
        int n = nh * 512 + r;
        const float* mpp = mp + ((size_t)b * NN + n) * 3;
        const float* tgp = tg + ((size_t)b * NN + n) * 3;
        float m0 = mpp[0], m1 = mpp[1], m2 = mpp[2];
        float g0 = tgp[0], g1 = tgp[1], g2 = tgp[2];
        float Q[17];
        Q[0] = 1.0f;
        Q[1] = m0 * m0 + m1 * m1 + m2 * m2 + g0 * g0 + g1 * g1 + g2 * g2;
        Q[2] = g0; Q[3] = g1; Q[4] = g2;
        Q[5] = m0; Q[6] = m1; Q[7] = m2;
        Q[8]  = m0 * g0; Q[9]  = m0 * g1; Q[10] = m0 * g2;
        Q[11] = m1 * g0; Q[12] = m1 * g1; Q[13] = m1 * g2;
        Q[14] = m2 * g0; Q[15] = m2 * g1; Q[16] = m2 * g2;
        emit_row(smB, r, Q, false);
    }

    // ---- build P rows (threads < 64) into smA ----
    if (t < 64) {
        int i = b * MM + mt * 64 + t;
        float4 q = reinterpret_cast<const float4*>(pred_r)[i];
        float t0 = points[3 * i + 0] + pred_t[3 * i + 0];
        float t1 = points[3 * i + 1] + pred_t[3 * i + 1];
        float t2 = points[3 * i + 2] + pred_t[3 * i + 2];
        float o[12];
        quat_to_Rt(q.x, q.y, q.z, q.w, t0, t1, t2, o);
        float w0 = o[0] * t0 + o[1] * t1 + o[2] * t2;
        float w1 = o[3] * t0 + o[4] * t1 + o[5] * t2;
        float w2 = o[6] * t0 + o[7] * t1 + o[8] * t2;
        float P[17];
        P[0] = t0 * t0 + t1 * t1 + t2 * t2;
        P[1] = 1.0f;
        P[2] = -2.0f * t0; P[3] = -2.0f * t1; P[4] = -2.0f * t2;
        P[5] = 2.0f * w0;  P[6] = 2.0f * w1;  P[7] = 2.0f * w2;
        #pragma unroll
        for (int u = 0; u < 9; u++) P[8 + u] = -2.0f * o[u];
        emit_row(smA, t, P, true);
    }

    // ---- argmax + R_best: only the 32 (nh==0,mt==0) blocks ----
    if (nh == 0 && mt == 0) {
        __shared__ float sv[128];
        __shared__ int   si[128];
        float cmax = -1e30f; int cidx = 0;
        #pragma unroll
        for (int k = 0; k < 8; k++) {                 // increasing m -> first-max tie-break
            int m = t + k * 128;
            float c = fmaxf(pred_c[b * MM + m], 1e-6f);
            if (c > cmax) { cmax = c; cidx = m; }
        }
        sv[t] = cmax; si[t] = cidx;
        __syncthreads();
        #pragma unroll
        for (int off = 64; off > 0; off >>= 1) {
            if (t < off) {
                if (sv[t + off] > sv[t] || (sv[t + off] == sv[t] && si[t + off] < si[t])) {
                    sv[t] = sv[t + off]; si[t] = si[t + off];
                }
            }
            __syncthreads();
        }
        if (t == 0) {
            int which = si[0];
            g_which[b] = which;
            int i = b * MM + which;
            float4 q = reinterpret_cast<const float4*>(pred_r)[i];
            float t0 = points[3 * i + 0] + pred_t[3 * i + 0];
            float t1 = points[3 * i + 1] + pred_t[3 * i + 1];
            float t2 = points[3 * i + 2] + pred_t[3 * i + 2];
            float o[12];
            quat_to_Rt(q.x, q.y, q.z, q.w, t0, t1, t2, o);
            #pragma unroll
            for (int j = 0; j < 12; j++) g_Rbest[b][j] = o[j];
        }
    }
    __syncthreads();

    // ---- A fragments: warp's m16 tile, 4 k-steps ----
    u32 afr[4][4];
    {
        int rowl = w * 16 + (lane & 7) + (((lane >> 3) & 1) << 3);
        int csel = lane >> 4;
        u32 rx = (u32)((rowl & 7) << 4);
        #pragma unroll
        for (int K = 0; K < 4; K++) {
            u32 off = ((u32)(rowl * 128 + (K * 2 + csel) * 16)) ^ rx;
            ldsm_x4(afr[K][0], afr[K][1], afr[K][2], afr[K][3], aA + off);
        }
    }

    // ---- main loop: 64 n8-tiles over the resident 512-row B ----
    float accL = 0.0f, accH = 0.0f;
    {
        int l4 = lane & 15;
        int brow = l4 & 7;
        int bcsel = l4 >> 3;
        u32 rx = (u32)(brow << 4);
        #pragma unroll 2
        for (int T = 0; T < 64; T++) {
            u32 bfr[4][2];
            int rowl = T * 8 + brow;
            #pragma unroll
            for (int K = 0; K < 4; K++) {
                u32 off = ((u32)(rowl * 128 + (K * 2 + bcsel) * 16)) ^ rx;
                ldsm_x2(bfr[K][0], bfr[K][1], aB + off);
            }
            float d0 = 0.f, d1 = 0.f, d2 = 0.f, d3 = 0.f;
            #pragma unroll
            for (int K = 0; K < 4; K++)
                mma16816(d0, d1, d2, d3,
                         afr[K][0], afr[K][1], afr[K][2], afr[K][3],
                         bfr[K][0], bfr[K][1]);
            accL += sqrt_approx(fmaxf(d0, 0.f)) + sqrt_approx(fmaxf(d1, 0.f));
            accH += sqrt_approx(fmaxf(d2, 0.f)) + sqrt_approx(fmaxf(d3, 0.f));
        }
    }

    // ---- quad reduce (cols distributed over 4 lanes of each group) ----
    accL += __shfl_xor_sync(0xffffffffu, accL, 1);
    accL += __shfl_xor_sync(0xffffffffu, accL, 2);
    accH += __shfl_xor_sync(0xffffffffu, accH, 1);
    accH += __shfl_xor_sync(0xffffffffu, accH, 2);
    if ((lane & 3) == 0) {
        int row = mt * 64 + w * 16 + (lane >> 2);
        g_part[nh][b * MM + row]     = accL;
        g_part[nh][b * MM + row + 8] = accH;
    }
}

// ---------------- K2: combine + transform + final scalars (fused) ----------------
// blocks 0..255: combine slice -> fence -> count -> 2 transform rows each.
// block 256: waits for count==256, reduces final scalars, resets counter.
__global__ void __launch_bounds__(128) k_fin(const float* __restrict__ wptr,
                                             const float* __restrict__ pred_c,
                                             const float* __restrict__ points,
                                             const float* __restrict__ target,
                                             float* __restrict__ out) {
    int t = threadIdx.x;
    if (blockIdx.x == 256) {
        if (t == 0) { while (atomicAdd(&g_done, 0) < 256) { } }
        __syncthreads();
        __shared__ float sbuf[128];
        __shared__ float sdb;
        sbuf[t] = g_lpart[t] + g_lpart[t + 128];
        if (t < 32) {
            float db = g_dish[t * MM + g_which[t]];
            #pragma unroll
            for (int off = 16; off > 0; off >>= 1)
                db += __shfl_down_sync(0xffffffffu, db, off);
            if (t == 0) sdb = db;
        }
        __syncthreads();
        #pragma unroll
        for (int off = 64; off > 0; off >>= 1) {
            if (t < off) sbuf[t] += sbuf[t + off];
            __syncthreads();
        }
        if (t == 0) {
            out[0] = sbuf[0] / (float)(BB * MM);
            out[1] = sdb * (1.0f / (float)NN) / (float)BB;
            g_done = 0;   // self-reset for graph replay
        }
        return;
    }

    // ---- combine slice ----
    int i = blockIdx.x * 128 + t;
    float wv = *wptr;
    float dsum = g_part[0][i] + g_part[1][i];
    g_dish[i] = dsum;
    float c = fmaxf(pred_c[i], 1e-6f);
    float term = dsum * (1.0f / (float)NN) * c - wv * __logf(c);

    __shared__ float sbuf[128];
    sbuf[t] = term;
    __syncthreads();
    #pragma unroll
    for (int off = 64; off > 0; off >>= 1) {
        if (t < off) sbuf[t] += sbuf[t + off];
        __syncthreads();
    }
    if (t == 0) {
        g_lpart[blockIdx.x] = sbuf[0];
        __threadfence();
        atomicAdd(&g_done, 1);
    }

    // ---- transform: 2 rows per thread ----
    #pragma unroll
    for (int k2 = 0; k2 < 2; k2++) {
        int id = blockIdx.x * 128 + t + k2 * 32768;
        int b = id >> 11;
        int r = id & 2047;

        const float4* rb4 = reinterpret_cast<const float4*>(&g_Rbest[b][0]);
        float4 ra = rb4[0], rbv = rb4[1], rc = rb4[2];
        float R0 = ra.x, R1 = ra.y, R2 = ra.z, R3 = ra.w;
        float R4 = rbv.x, R5 = rbv.y, R6 = rbv.z, R7 = rbv.w;
        float R8 = rc.x,  T0 = rc.y,  T1 = rc.z,  T2 = rc.w;

        const float* src;
        float* dst;
        if (r < MM) {
            src = points + ((size_t)b * MM + r) * 3;
            dst = out + 2 + ((size_t)b * MM + r) * 3;
        } else {
            int n = r - MM;
            src = target + ((size_t)b * NN + n) * 3;
            dst = out + 2 + (size_t)BB * MM * 3 + ((size_t)b * NN + n) * 3;
        }
        float d0 = src[0] - T0;
        float d1 = src[1] - T1;
        float d2 = src[2] - T2;
        dst[0] = d0 * R0 + d1 * R3 + d2 * R6;
        dst[1] = d0 * R1 + d1 * R4 + d2 * R7;
        dst[2] = d0 * R2 + d1 * R5 + d2 * R8;
    }
}

// ---------------- launch ----------------
extern "C" void kernel_launch(void* const* d_in, const int* in_sizes, int n_in,
                              void* d_out, int out_size) {
    const float* pred_r       = (const float*)d_in[0];
    const float* pred_t       = (const float*)d_in[1];
    const float* pred_c       = (const float*)d_in[2];
    const float* target       = (const float*)d_in[3];
    const float* model_points = (const float*)d_in[4];
    // d_in[5] = idx (unused, refine path)
    const float* points       = (const float*)d_in[6];
    const float* wptr         = (const float*)d_in[7];
    // d_in[8] = refine (unused)
    float* out = (float*)d_out;

    const int dyn = (2048 + 16384) * 4;   // 72 KB
    cudaFuncSetAttribute(k_main, cudaFuncAttributeMaxDynamicSharedMemorySize, dyn);
    k_main<<<dim3(2, 16, BB), 128, dyn>>>(pred_r, pred_t, pred_c, points, model_points, target);
    k_fin<<<257, 128>>>(wptr, pred_c, points, target, out);
}

// round 16
// speedup vs baseline: 1.1298x; 1.1298x over previous
#include <cuda_runtime.h>
#include <math.h>

#define BB 32
#define MM 1024
#define NN 1024
#define SS 4      // n-split factor
#define TN 256    // n per block tile (SS*TN = NN)
#define NP (TN/2) // n-pairs per tile = 128
#define MS 8      // m-split: 8 groups of 128 m's; 1 m per thread

typedef unsigned long long u64;

// ---------------- scratch (no allocations allowed) ----------------
__device__ float g_part[SS][BB * MM];       // partial sqrt-sums per n-chunk
__device__ float g_dish[BB * MM];           // sum over all n (not yet /N)
__device__ float g_lpart[128];              // per-combine-block loss partials
__device__ int   g_which[BB];
__device__ float g_Rbest[BB][12];           // R row-major (9) + t_best (3); 48B rows
__device__ int   g_done;                    // zero-init; self-reset each run

// ---------------- f32x2 helpers (sm_103a packed fp32) ----------------
__device__ __forceinline__ u64 pack2(float a, float b) {
    u64 r; asm("mov.b64 %0, {%1,%2};" : "=l"(r) : "f"(a), "f"(b)); return r;
}
__device__ __forceinline__ void unpack2(u64 v, float& a, float& b) {
    asm("mov.b64 {%0,%1}, %2;" : "=f"(a), "=f"(b) : "l"(v));
}
__device__ __forceinline__ u64 fma2(u64 a, u64 b, u64 c) {
    u64 r; asm("fma.rn.f32x2 %0, %1, %2, %3;" : "=l"(r) : "l"(a), "l"(b), "l"(c)); return r;
}
__device__ __forceinline__ u64 add2(u64 a, u64 b) {
    u64 r; asm("add.rn.f32x2 %0, %1, %2;" : "=l"(r) : "l"(a), "l"(b)); return r;
}
__device__ __forceinline__ u64 mul2(u64 a, u64 b) {
    u64 r; asm("mul.rn.f32x2 %0, %1, %2;" : "=l"(r) : "l"(a), "l"(b)); return r;
}
__device__ __forceinline__ float sqrt_approx(float x) {
    float r; asm("sqrt.approx.f32 %0, %1;" : "=f"(r) : "f"(x)); return r;
}

// quat (xyzw) + t -> 12 floats: R row-major then t
__device__ __forceinline__ void quat_to_Rt(float qx, float qy, float qz, float qw,
                                           float t0, float t1, float t2, float* o) {
    float nrm = sqrtf(qx * qx + qy * qy + qz * qz + qw * qw);
    float inv = __fdividef(1.0f, nrm + 1e-8f);
    qx *= inv; qy *= inv; qz *= inv; qw *= inv;
    o[0] = 1.0f - 2.0f * (qy * qy + qz * qz);
    o[1] = 2.0f * (qx * qy - qz * qw);
    o[2] = 2.0f * (qx * qz + qy * qw);
    o[3] = 2.0f * (qx * qy + qz * qw);
    o[4] = 1.0f - 2.0f * (qx * qx + qz * qz);
    o[5] = 2.0f * (qy * qz - qx * qw);
    o[6] = 2.0f * (qx * qz - qy * qw);
    o[7] = 2.0f * (qy * qz + qx * qw);
    o[8] = 1.0f - 2.0f * (qx * qx + qy * qy);
    o[9] = t0; o[10] = t1; o[11] = t2;
}

// ---------------- K1: fused prep + 33.5M-pair distance kernel (R8, proven) ----------------
// grid (SS, MS, BB), 128 threads. Thread t owns m = t + h*128.
// f32x2 lanes carry (n, n+1) pairs; R/t constants are lane-splat.
// Tile stores NEGATED tg so the translate-subtract is a single add2.
__global__ void __launch_bounds__(128, 10) k_main(const float* __restrict__ pred_r,
                                                  const float* __restrict__ pred_t,
                                                  const float* __restrict__ pred_c,
                                                  const float* __restrict__ points,
                                                  const float* __restrict__ mp,
                                                  const float* __restrict__ tg) {
    const int s = blockIdx.x;
    const int h = blockIdx.y;
    const int b = blockIdx.z;
    const int t = threadIdx.x;

    __shared__ __align__(16) u64 sm[NP][6];

    // ---- n-tile load: every thread packs n-pair (2t, 2t+1) via float2 loads ----
    {
        const float2* mb = reinterpret_cast<const float2*>(mp + (size_t)(b * NN + s * TN) * 3);
        const float2* gb = reinterpret_cast<const float2*>(tg + (size_t)(b * NN + s * TN) * 3);
        float2 A0 = mb[3 * t], A1 = mb[3 * t + 1], A2 = mb[3 * t + 2];
        float2 G0 = gb[3 * t], G1 = gb[3 * t + 1], G2 = gb[3 * t + 2];
        sm[t][0] = pack2(A0.x, A1.y);
        sm[t][1] = pack2(A0.y, A2.x);
        sm[t][2] = pack2(A1.x, A2.y);
        sm[t][3] = pack2(-G0.x, -G1.y);
        sm[t][4] = pack2(-G0.y, -G2.x);
        sm[t][5] = pack2(-G1.x, -G2.y);
    }

    // ---- inline prep: R/t for this thread's single m, lane-splat constants ----
    u64 C[12];
    {
        int m = t + h * 128;
        int i = b * MM + m;
        float4 q = reinterpret_cast<const float4*>(pred_r)[i];
        float t0 = points[3 * i + 0] + pred_t[3 * i + 0];
        float t1 = points[3 * i + 1] + pred_t[3 * i + 1];
        float t2 = points[3 * i + 2] + pred_t[3 * i + 2];
        float o[12];
        quat_to_Rt(q.x, q.y, q.z, q.w, t0, t1, t2, o);
        #pragma unroll
        for (int j = 0; j < 12; j++) C[j] = pack2(o[j], o[j]);
    }

    // ---- argmax + R_best: only the 32 (s==0,h==0) blocks ----
    if (s == 0 && h == 0) {
        __shared__ float sv[128];
        __shared__ int   si[128];
        float cmax = -1e30f; int cidx = 0;
        #pragma unroll
        for (int k = 0; k < 8; k++) {                 // increasing m -> first-max tie-break
            int m = t + k * 128;
            float c = fmaxf(pred_c[b * MM + m], 1e-6f);
            if (c > cmax) { cmax = c; cidx = m; }
        }
        sv[t] = cmax; si[t] = cidx;
        __syncthreads();
        #pragma unroll
        for (int off = 64; off > 0; off >>= 1) {
            if (t < off) {
                if (sv[t + off] > sv[t] || (sv[t + off] == sv[t] && si[t + off] < si[t])) {
                    sv[t] = sv[t + off]; si[t] = si[t + off];
                }
            }
            __syncthreads();
        }
        if (t == 0) {
            int which = si[0];
            g_which[b] = which;
            int i = b * MM + which;
            float4 q = reinterpret_cast<const float4*>(pred_r)[i];
            float t0 = points[3 * i + 0] + pred_t[3 * i + 0];
            float t1 = points[3 * i + 1] + pred_t[3 * i + 1];
            float t2 = points[3 * i + 2] + pred_t[3 * i + 2];
            float o[12];
            quat_to_Rt(q.x, q.y, q.z, q.w, t0, t1, t2, o);
            #pragma unroll
            for (int j = 0; j < 12; j++) g_Rbest[b][j] = o[j];
        }
    }
    __syncthreads();   // covers sm tile for all blocks

    // ---- main loop: 2 cells per iter (1 m x 2 packed n's), dual accumulators ----
    float accA = 0.0f, accB = 0.0f;

    #pragma unroll 4
    for (int n = 0; n < NP; n++) {
        ulonglong2 p01 = *reinterpret_cast<const ulonglong2*>(&sm[n][0]);
        ulonglong2 p23 = *reinterpret_cast<const ulonglong2*>(&sm[n][2]);
        ulonglong2 p45 = *reinterpret_cast<const ulonglong2*>(&sm[n][4]);
        u64 m0 = p01.x, m1 = p01.y, m2 = p23.x;
        u64 v0 = p23.y, v1 = p45.x, v2 = p45.y;     // v = -tg
        u64 s0 = add2(v0, C[9]);                    // t - tg
        u64 s1 = add2(v1, C[10]);
        u64 s2 = add2(v2, C[11]);
        u64 d0 = fma2(m0, C[0], fma2(m1, C[3], fma2(m2, C[6], s0)));
        u64 d1 = fma2(m0, C[1], fma2(m1, C[4], fma2(m2, C[7], s1)));
        u64 d2 = fma2(m0, C[2], fma2(m1, C[5], fma2(m2, C[8], s2)));
        u64 sq = fma2(d0, d0, fma2(d1, d1, mul2(d2, d2)));
        float sa, sb; unpack2(sq, sa, sb);
        accA += sqrt_approx(sa);
        accB += sqrt_approx(sb);
    }

    g_part[s][(size_t)b * MM + h * 128 + t] = accA + accB;
}

// ---------------- K2: fused combine + transform + final scalars ----------------
// 384 blocks x 256 threads.
// blocks 0..127:   combine 256 items each -> g_lpart[bid]; last ticket does scalars.
// blocks 128..383: transform, 1 row/thread (65536 rows total).
__global__ void __launch_bounds__(256) k_fin(const float* __restrict__ wptr,
                                             const float* __restrict__ pred_c,
                                             const float* __restrict__ points,
                                             const float* __restrict__ target,
                                             float* __restrict__ out) {
    const int t = threadIdx.x;
    const int bid = blockIdx.x;

    if (bid < 128) {
        // ---- combine slice ----
        int i = bid * 256 + t;
        float wv = *wptr;
        float dsum = 0.0f;
        #pragma unroll
        for (int ss = 0; ss < SS; ss++) dsum += g_part[ss][i];
        g_dish[i] = dsum;
        float c = fmaxf(pred_c[i], 1e-6f);
        float term = dsum * (1.0f / (float)NN) * c - wv * __logf(c);

        __shared__ float sbuf[256];
        __shared__ int sticket;
        sbuf[t] = term;
        __syncthreads();
        #pragma unroll
        for (int off = 128; off > 0; off >>= 1) {
            if (t < off) sbuf[t] += sbuf[t + off];
            __syncthreads();
        }
        if (t == 0) {
            g_lpart[bid] = sbuf[0];
            __threadfence();
            sticket = atomicAdd(&g_done, 1);
        }
        __syncthreads();

        if (sticket == 127) {
            // last combine block: all g_lpart/g_dish published. Final scalars.
            __threadfence();
            __shared__ float fbuf[128];
            __shared__ float sdb;
            if (t < 128) fbuf[t] = g_lpart[t];
            if (t < 32) {
                float db = g_dish[t * MM + g_which[t]];
                #pragma unroll
                for (int off = 16; off > 0; off >>= 1)
                    db += __shfl_down_sync(0xffffffffu, db, off);
                if (t == 0) sdb = db;
            }
            __syncthreads();
            #pragma unroll
            for (int off = 64; off > 0; off >>= 1) {
                if (t < off) fbuf[t] += fbuf[t + off];
                __syncthreads();
            }
            if (t == 0) {
                out[0] = fbuf[0] / (float)(BB * MM);
                out[1] = sdb * (1.0f / (float)NN) / (float)BB;
                g_done = 0;   // self-reset for graph replay
            }
        }
        return;
    }

    // ---- transform: 1 row per thread ----
    int id = (bid - 128) * 256 + t;    // 256 blocks x 256 = 65536 = BB*(MM+NN)
    int b = id >> 11;
    int r = id & 2047;

    const float4* rb4 = reinterpret_cast<const float4*>(&g_Rbest[b][0]);
    float4 ra = rb4[0], rbv = rb4[1], rc = rb4[2];
    float R0 = ra.x, R1 = ra.y, R2 = ra.z, R3 = ra.w;
    float R4 = rbv.x, R5 = rbv.y, R6 = rbv.z, R7 = rbv.w;
    float R8 = rc.x,  T0 = rc.y,  T1 = rc.z,  T2 = rc.w;

    const float* src;
    float* dst;
    if (r < MM) {
        src = points + ((size_t)b * MM + r) * 3;
        dst = out + 2 + ((size_t)b * MM + r) * 3;
    } else {
        int n = r - MM;
        src = target + ((size_t)b * NN + n) * 3;
        dst = out + 2 + (size_t)BB * MM * 3 + ((size_t)b * NN + n) * 3;
    }
    float d0 = src[0] - T0;
    float d1 = src[1] - T1;
    float d2 = src[2] - T2;
    dst[0] = d0 * R0 + d1 * R3 + d2 * R6;
    dst[1] = d0 * R1 + d1 * R4 + d2 * R7;
    dst[2] = d0 * R2 + d1 * R5 + d2 * R8;
}

// ---------------- launch ----------------
extern "C" void kernel_launch(void* const* d_in, const int* in_sizes, int n_in,
                              void* d_out, int out_size) {
    const float* pred_r       = (const float*)d_in[0];
    const float* pred_t       = (const float*)d_in[1];
    const float* pred_c       = (const float*)d_in[2];
    const float* target       = (const float*)d_in[3];
    const float* model_points = (const float*)d_in[4];
    // d_in[5] = idx (unused, refine path)
    const float* points       = (const float*)d_in[6];
    const float* wptr         = (const float*)d_in[7];
    // d_in[8] = refine (unused)
    float* out = (float*)d_out;

    k_main<<<dim3(SS, MS, BB), 128>>>(pred_r, pred_t, pred_c, points, model_points, target);
    k_fin<<<384, 256>>>(wptr, pred_c, points, target, out);
}

// round 17
// speedup vs baseline: 1.1309x; 1.0010x over previous
#include <cuda_runtime.h>
#include <math.h>

#define BB 32
#define MM 1024
#define NN 1024
#define SS 4      // n-split factor
#define TN 256    // n per block tile (SS*TN = NN)
#define NP (TN/2) // n-pairs per tile = 128
#define MS 8      // m-split: 8 groups of 128 m's; 1 m per thread

typedef unsigned long long u64;

// ---------------- scratch (no allocations allowed) ----------------
__device__ float g_part[SS][BB * MM];       // partial sqrt-sums per n-chunk
__device__ float g_dish[BB * MM];           // sum over all n (not yet /N)
__device__ float g_lpart[128];              // per-combine-block loss partials
__device__ int   g_which[BB];
__device__ float g_Rbest[BB][12];           // R row-major (9) + t_best (3); 48B rows
__device__ int   g_rdy[BB];                 // per-b release flag for g_Rbest (reset in k_fin)
__device__ int   g_done;                    // combine ticket; self-reset each run

// ---------------- f32x2 helpers (sm_103a packed fp32) ----------------
__device__ __forceinline__ u64 pack2(float a, float b) {
    u64 r; asm("mov.b64 %0, {%1,%2};" : "=l"(r) : "f"(a), "f"(b)); return r;
}
__device__ __forceinline__ void unpack2(u64 v, float& a, float& b) {
    asm("mov.b64 {%0,%1}, %2;" : "=f"(a), "=f"(b) : "l"(v));
}
__device__ __forceinline__ u64 fma2(u64 a, u64 b, u64 c) {
    u64 r; asm("fma.rn.f32x2 %0, %1, %2, %3;" : "=l"(r) : "l"(a), "l"(b), "l"(c)); return r;
}
__device__ __forceinline__ u64 add2(u64 a, u64 b) {
    u64 r; asm("add.rn.f32x2 %0, %1, %2;" : "=l"(r) : "l"(a), "l"(b)); return r;
}
__device__ __forceinline__ u64 mul2(u64 a, u64 b) {
    u64 r; asm("mul.rn.f32x2 %0, %1, %2;" : "=l"(r) : "l"(a), "l"(b)); return r;
}
__device__ __forceinline__ float sqrt_approx(float x) {
    float r; asm("sqrt.approx.f32 %0, %1;" : "=f"(r) : "f"(x)); return r;
}

// quat (xyzw) + t -> 12 floats: R row-major then t
__device__ __forceinline__ void quat_to_Rt(float qx, float qy, float qz, float qw,
                                           float t0, float t1, float t2, float* o) {
    float nrm = sqrtf(qx * qx + qy * qy + qz * qz + qw * qw);
    float inv = __fdividef(1.0f, nrm + 1e-8f);
    qx *= inv; qy *= inv; qz *= inv; qw *= inv;
    o[0] = 1.0f - 2.0f * (qy * qy + qz * qz);
    o[1] = 2.0f * (qx * qy - qz * qw);
    o[2] = 2.0f * (qx * qz + qy * qw);
    o[3] = 2.0f * (qx * qy + qz * qw);
    o[4] = 1.0f - 2.0f * (qx * qx + qz * qz);
    o[5] = 2.0f * (qy * qz - qx * qw);
    o[6] = 2.0f * (qx * qz - qy * qw);
    o[7] = 2.0f * (qy * qz + qx * qw);
    o[8] = 1.0f - 2.0f * (qx * qx + qy * qy);
    o[9] = t0; o[10] = t1; o[11] = t2;
}

// ---------------- K1: prep + distances + argmax + transform (single wave) ----------------
// grid (SS, MS, BB) = 1024 blocks, 128 threads, all co-resident (occ bound 10).
// Thread t owns m = t + h*128. f32x2 lanes carry (n, n+1) pairs; constants lane-splat.
// Tile stores NEGATED tg so the translate-subtract is a single add2.
// Epilogue: each block transforms 64 rows, gated on per-b release flag set by the
// argmax blocks early in the same wave (flag is always already set by epilogue time).
__global__ void __launch_bounds__(128, 10) k_main(const float* __restrict__ pred_r,
                                                  const float* __restrict__ pred_t,
                                                  const float* __restrict__ pred_c,
                                                  const float* __restrict__ points,
                                                  const float* __restrict__ mp,
                                                  const float* __restrict__ tg,
                                                  float* __restrict__ out) {
    const int s = blockIdx.x;
    const int h = blockIdx.y;
    const int b = blockIdx.z;
    const int t = threadIdx.x;

    __shared__ __align__(16) u64 sm[NP][6];

    // ---- n-tile load: every thread packs n-pair (2t, 2t+1) via float2 loads ----
    {
        const float2* mb = reinterpret_cast<const float2*>(mp + (size_t)(b * NN + s * TN) * 3);
        const float2* gb = reinterpret_cast<const float2*>(tg + (size_t)(b * NN + s * TN) * 3);
        float2 A0 = mb[3 * t], A1 = mb[3 * t + 1], A2 = mb[3 * t + 2];
        float2 G0 = gb[3 * t], G1 = gb[3 * t + 1], G2 = gb[3 * t + 2];
        sm[t][0] = pack2(A0.x, A1.y);
        sm[t][1] = pack2(A0.y, A2.x);
        sm[t][2] = pack2(A1.x, A2.y);
        sm[t][3] = pack2(-G0.x, -G1.y);
        sm[t][4] = pack2(-G0.y, -G2.x);
        sm[t][5] = pack2(-G1.x, -G2.y);
    }

    // ---- inline prep: R/t for this thread's single m, lane-splat constants ----
    u64 C[12];
    {
        int m = t + h * 128;
        int i = b * MM + m;
        float4 q = reinterpret_cast<const float4*>(pred_r)[i];
        float t0 = points[3 * i + 0] + pred_t[3 * i + 0];
        float t1 = points[3 * i + 1] + pred_t[3 * i + 1];
        float t2 = points[3 * i + 2] + pred_t[3 * i + 2];
        float o[12];
        quat_to_Rt(q.x, q.y, q.z, q.w, t0, t1, t2, o);
        #pragma unroll
        for (int j = 0; j < 12; j++) C[j] = pack2(o[j], o[j]);
    }

    // ---- argmax + R_best + release flag: only the 32 (s==0,h==0) blocks ----
    if (s == 0 && h == 0) {
        __shared__ float sv[128];
        __shared__ int   si[128];
        float cmax = -1e30f; int cidx = 0;
        #pragma unroll
        for (int k = 0; k < 8; k++) {                 // increasing m -> first-max tie-break
            int m = t + k * 128;
            float c = fmaxf(pred_c[b * MM + m], 1e-6f);
            if (c > cmax) { cmax = c; cidx = m; }
        }
        sv[t] = cmax; si[t] = cidx;
        __syncthreads();
        #pragma unroll
        for (int off = 64; off > 0; off >>= 1) {
            if (t < off) {
                if (sv[t + off] > sv[t] || (sv[t + off] == sv[t] && si[t + off] < si[t])) {
                    sv[t] = sv[t + off]; si[t] = si[t + off];
                }
            }
            __syncthreads();
        }
        if (t == 0) {
            int which = si[0];
            g_which[b] = which;
            int i = b * MM + which;
            float4 q = reinterpret_cast<const float4*>(pred_r)[i];
            float t0 = points[3 * i + 0] + pred_t[3 * i + 0];
            float t1 = points[3 * i + 1] + pred_t[3 * i + 1];
            float t2 = points[3 * i + 2] + pred_t[3 * i + 2];
            float o[12];
            quat_to_Rt(q.x, q.y, q.z, q.w, t0, t1, t2, o);
            #pragma unroll
            for (int j = 0; j < 12; j++) g_Rbest[b][j] = o[j];
            __threadfence();               // release
            g_rdy[b] = 1;
            __threadfence();
        }
    }
    __syncthreads();   // covers sm tile for all blocks

    // ---- main loop: 2 cells per iter (1 m x 2 packed n's), dual accumulators ----
    float accA = 0.0f, accB = 0.0f;

    #pragma unroll 4
    for (int n = 0; n < NP; n++) {
        ulonglong2 p01 = *reinterpret_cast<const ulonglong2*>(&sm[n][0]);
        ulonglong2 p23 = *reinterpret_cast<const ulonglong2*>(&sm[n][2]);
        ulonglong2 p45 = *reinterpret_cast<const ulonglong2*>(&sm[n][4]);
        u64 m0 = p01.x, m1 = p01.y, m2 = p23.x;
        u64 v0 = p23.y, v1 = p45.x, v2 = p45.y;     // v = -tg
        u64 s0 = add2(v0, C[9]);                    // t - tg
        u64 s1 = add2(v1, C[10]);
        u64 s2 = add2(v2, C[11]);
        u64 d0 = fma2(m0, C[0], fma2(m1, C[3], fma2(m2, C[6], s0)));
        u64 d1 = fma2(m0, C[1], fma2(m1, C[4], fma2(m2, C[7], s1)));
        u64 d2 = fma2(m0, C[2], fma2(m1, C[5], fma2(m2, C[8], s2)));
        u64 sq = fma2(d0, d0, fma2(d1, d1, mul2(d2, d2)));
        float sa, sb; unpack2(sq, sa, sb);
        accA += sqrt_approx(sa);
        accB += sqrt_approx(sb);
    }

    g_part[s][(size_t)b * MM + h * 128 + t] = accA + accB;

    // ---- epilogue: 64 transform rows per block (flag long since set) ----
    if (t < 64) {
        int blin = (b * MS + h) * SS + s;          // 0..1023
        int id = blin * 64 + t;                    // 0..65535 = BB*(MM+NN)
        int b2 = id >> 11;
        int r  = id & 2047;

        while (((volatile int*)g_rdy)[b2] == 0) { }
        __threadfence();                           // acquire

        const float4* rb4 = reinterpret_cast<const float4*>(&g_Rbest[b2][0]);
        float4 ra = rb4[0], rbv = rb4[1], rc = rb4[2];
        float R0 = ra.x, R1 = ra.y, R2 = ra.z, R3 = ra.w;
        float R4 = rbv.x, R5 = rbv.y, R6 = rbv.z, R7 = rbv.w;
        float R8 = rc.x,  T0 = rc.y,  T1 = rc.z,  T2 = rc.w;

        const float* src;
        float* dst;
        if (r < MM) {
            src = points + ((size_t)b2 * MM + r) * 3;
            dst = out + 2 + ((size_t)b2 * MM + r) * 3;
        } else {
            int n = r - MM;
            src = tg + ((size_t)b2 * NN + n) * 3;
            dst = out + 2 + (size_t)BB * MM * 3 + ((size_t)b2 * NN + n) * 3;
        }
        float d0 = src[0] - T0;
        float d1 = src[1] - T1;
        float d2 = src[2] - T2;
        dst[0] = d0 * R0 + d1 * R3 + d2 * R6;
        dst[1] = d0 * R1 + d1 * R4 + d2 * R7;
        dst[2] = d0 * R2 + d1 * R5 + d2 * R8;
    }
}

// ---------------- K2: combine + final scalars ----------------
// 128 blocks x 256 threads; last ticket block reduces final scalars and resets flags.
__global__ void __launch_bounds__(256) k_fin(const float* __restrict__ wptr,
                                             const float* __restrict__ pred_c,
                                             float* __restrict__ out) {
    const int t = threadIdx.x;
    const int bid = blockIdx.x;

    // ---- combine slice ----
    int i = bid * 256 + t;
    float wv = *wptr;
    float dsum = 0.0f;
    #pragma unroll
    for (int ss = 0; ss < SS; ss++) dsum += g_part[ss][i];
    g_dish[i] = dsum;
    float c = fmaxf(pred_c[i], 1e-6f);
    float term = dsum * (1.0f / (float)NN) * c - wv * __logf(c);

    __shared__ float sbuf[256];
    __shared__ int sticket;
    sbuf[t] = term;
    __syncthreads();
    #pragma unroll
    for (int off = 128; off > 0; off >>= 1) {
        if (t < off) sbuf[t] += sbuf[t + off];
        __syncthreads();
    }
    if (t == 0) {
        g_lpart[bid] = sbuf[0];
        __threadfence();
        sticket = atomicAdd(&g_done, 1);
    }
    __syncthreads();

    if (sticket == 127) {
        // all g_lpart/g_dish published. Final scalars + flag reset for graph replay.
        __threadfence();
        __shared__ float fbuf[128];
        __shared__ float sdb;
        if (t < 128) fbuf[t] = g_lpart[t];
        if (t < 32) {
            float db = g_dish[t * MM + g_which[t]];
            #pragma unroll
            for (int off = 16; off > 0; off >>= 1)
                db += __shfl_down_sync(0xffffffffu, db, off);
            if (t == 0) sdb = db;
        }
        if (t >= 128 && t < 128 + BB) g_rdy[t - 128] = 0;   // reset release flags
        __syncthreads();
        #pragma unroll
        for (int off = 64; off > 0; off >>= 1) {
            if (t < off) fbuf[t] += fbuf[t + off];
            __syncthreads();
        }
        if (t == 0) {
            out[0] = fbuf[0] / (float)(BB * MM);
            out[1] = sdb * (1.0f / (float)NN) / (float)BB;
            g_done = 0;   // self-reset for graph replay
        }
    }
}

// ---------------- launch ----------------
extern "C" void kernel_launch(void* const* d_in, const int* in_sizes, int n_in,
                              void* d_out, int out_size) {
    const float* pred_r       = (const float*)d_in[0];
    const float* pred_t       = (const float*)d_in[1];
    const float* pred_c       = (const float*)d_in[2];
    const float* target       = (const float*)d_in[3];
    const float* model_points = (const float*)d_in[4];
    // d_in[5] = idx (unused, refine path)
    const float* points       = (const float*)d_in[6];
    const float* wptr         = (const float*)d_in[7];
    // d_in[8] = refine (unused)
    float* out = (float*)d_out;

    k_main<<<dim3(SS, MS, BB), 128>>>(pred_r, pred_t, pred_c, points, model_points, target, out);
    k_fin<<<128, 256>>>(wptr, pred_c, out);
}